// round 8
// baseline (speedup 1.0000x reference)
#include <cuda_runtime.h>
#include <math.h>

#define B 64
#define T 4096
#define D 512
#define SPLITS 16
#define CHUNK (T / SPLITS)   // 256 rows of T per CTA
#define TS 8                 // tile rows per iteration (one per warp)
#define THREADS 256
#define RPV (D / 4)          // 128 float4 per row

// Scratch (no allocation allowed anywhere)
__device__ float g_k[B * D];                    // key = query @ W^T + b
__device__ float g_pm[B * SPLITS];              // partial max
__device__ float g_ps[B * SPLITS];              // partial sum
__device__ float g_pacc[B * SPLITS * D];        // partial weighted accumulators

// ---------------------------------------------------------------------------
// Kernel 1: k[b, d] = sum_j query[b, j] * W[d, j] + bias[d]
// grid = B blocks, 512 threads (one per output d). W (1 MB) stays in L2.
// ---------------------------------------------------------------------------
__global__ void key_kernel(const float* __restrict__ query,
                           const float* __restrict__ W,
                           const float* __restrict__ bias) {
    __shared__ float q_sh[D];
    int b = blockIdx.x;
    for (int i = threadIdx.x; i < D; i += blockDim.x) q_sh[i] = query[b * D + i];
    __syncthreads();
    int d = threadIdx.x;  // blockDim.x == 512
    const float4* Wrow = (const float4*)(W + (size_t)d * D);
    float sum = 0.f;
    #pragma unroll 8
    for (int j = 0; j < RPV; j++) {
        float4 w = Wrow[j];
        sum += w.x * q_sh[4 * j] + w.y * q_sh[4 * j + 1] +
               w.z * q_sh[4 * j + 2] + w.w * q_sh[4 * j + 3];
    }
    g_k[b * D + d] = sum + bias[d];
}

// ---------------------------------------------------------------------------
// Kernel 2: fused scores + masked online softmax + weighted accumulation.
// grid = (SPLITS, B). Each CTA streams attend_to[b, sp*CHUNK:(sp+1)*CHUNK, :]
// ONCE, double-buffered through shared memory, flash-style (m, s, acc) state.
// ---------------------------------------------------------------------------
__global__ __launch_bounds__(THREADS)
void attn_partial_kernel(const float* __restrict__ attend_to,
                         const int* __restrict__ mask) {   // bool widened to int32
    __shared__ float k_sh[D];
    __shared__ float tile[2][TS][D];     // double buffer: 2 x 16 KB
    __shared__ float sc_sh[TS];

    const int b    = blockIdx.y;
    const int sp   = blockIdx.x;
    const int tid  = threadIdx.x;
    const int wid  = tid >> 5;
    const int lane = tid & 31;
    const int t0   = sp * CHUNK;

    for (int i = tid; i < D; i += THREADS) k_sh[i] = g_k[b * D + i];

    // Fixed per-thread slice of each 8x512 tile: thread owns rows {lr, lr+4}
    // at float4 columns {lc, lc+1} (4 independent LDG.128 per tile).
    const int lr = tid / (RPV / 2);          // 0..3  (row group)
    const int lc = (tid % (RPV / 2)) * 2;    // even float4 column
    const float4* base = (const float4*)(attend_to + (size_t)b * T * D);
    const float4* src0 = base + (size_t)(t0 + lr) * RPV + lc;        // row lr
    const float4* src1 = base + (size_t)(t0 + lr + 4) * RPV + lc;    // row lr+4
    float4* dst0 = (float4*)&tile[0][lr][4 * lc];
    float4* dst1 = (float4*)&tile[0][lr + 4][4 * lc];
    const size_t tstep = (size_t)TS * RPV;   // advance TS rows

    // Prologue: load tile 0 into buffer 0
    { float4 a = src0[0], bq = src0[1], c = src1[0], dq = src1[1];
      dst0[0] = a; dst0[1] = bq; dst1[0] = c; dst1[1] = dq; }
    __syncthreads();

    float m = -INFINITY, s = 0.f;
    float acc0 = 0.f, acc1 = 0.f;
    const int c0 = tid, c1 = tid + THREADS;

    for (int tt = 0; tt < CHUNK; tt += TS) {
        const int buf  = (tt / TS) & 1;
        const int nbuf = buf ^ 1;
        const int doff = nbuf * (TS * D / 4);  // float4 offset between buffers

        // --- Prefetch next tile into the other buffer (independent of tile[buf]) ---
        if (tt + TS < CHUNK) {
            const float4* s0 = src0 + (size_t)(tt / TS + 1) * tstep;
            const float4* s1 = src1 + (size_t)(tt / TS + 1) * tstep;
            float4 a = s0[0], bq = s0[1], c = s1[0], dq = s1[1];
            float4* d0 = (float4*)&tile[0][0][0] + doff + (size_t)lr * RPV + lc;
            float4* d1 = d0 + 4 * RPV;
            d0[0] = a; d0[1] = bq; d1[0] = c; d1[1] = dq;
        }

        // --- Each warp computes the dot-product score for its row of tile[buf] ---
        {
            float partial = 0.f;
            #pragma unroll
            for (int j = 0; j < D / 32; j++) {       // 16 elems / lane
                int idx = j * 32 + lane;
                partial += tile[buf][wid][idx] * k_sh[idx];
            }
            #pragma unroll
            for (int off = 16; off; off >>= 1)
                partial += __shfl_xor_sync(0xffffffffu, partial, off);
            if (lane == 0) {
                int t = t0 + tt + wid;
                // mask[t, b], nonzero => masked out (-inf). Nonzero test is
                // correct for int32 0/1 and also for float32 0.0/1.0 bits.
                sc_sh[wid] = (__ldg(&mask[(size_t)t * B + b]) != 0)
                                 ? -INFINITY : partial;
            }
        }
        __syncthreads();

        // --- Online softmax update (block-consistent, redundant per thread) ---
        float tm = m;
        #pragma unroll
        for (int i = 0; i < TS; i++) tm = fmaxf(tm, sc_sh[i]);
        float corr = (m == -INFINITY) ? 0.f : __expf(m - tm);
        float p[TS];
        float psum = 0.f;
        #pragma unroll
        for (int i = 0; i < TS; i++) {
            float sc = sc_sh[i];
            p[i] = (sc == -INFINITY) ? 0.f : __expf(sc - tm);
            psum += p[i];
        }
        s = s * corr + psum;
        float a0 = acc0 * corr, a1 = acc1 * corr;
        #pragma unroll
        for (int i = 0; i < TS; i++) {
            a0 = fmaf(p[i], tile[buf][i][c0], a0);
            a1 = fmaf(p[i], tile[buf][i][c1], a1);
        }
        acc0 = a0; acc1 = a1;
        m = tm;
        __syncthreads();   // sc_sh + buffer handoff for next iteration
    }

    const int pi = b * SPLITS + sp;
    if (tid == 0) { g_pm[pi] = m; g_ps[pi] = s; }
    g_pacc[(size_t)pi * D + c0] = acc0;
    g_pacc[(size_t)pi * D + c1] = acc1;
}

// ---------------------------------------------------------------------------
// Kernel 3: combine SPLITS partials per batch row.
// ---------------------------------------------------------------------------
__global__ void combine_kernel(float* __restrict__ out) {
    const int b = blockIdx.x;
    const int tid = threadIdx.x;

    float M = -INFINITY;
    #pragma unroll
    for (int i = 0; i < SPLITS; i++) M = fmaxf(M, g_pm[b * SPLITS + i]);

    float wts[SPLITS];
    float stot = 0.f;
    #pragma unroll
    for (int i = 0; i < SPLITS; i++) {
        float mi = g_pm[b * SPLITS + i];
        float w = (mi == -INFINITY) ? 0.f : __expf(mi - M);
        wts[i] = w;
        stot += g_ps[b * SPLITS + i] * w;
    }
    float inv = 1.f / stot;

    for (int c = tid; c < D; c += blockDim.x) {
        float sum = 0.f;
        #pragma unroll
        for (int i = 0; i < SPLITS; i++)
            sum += g_pacc[(size_t)(b * SPLITS + i) * D + c] * wts[i];
        out[b * D + c] = sum * inv;
    }
}

// ---------------------------------------------------------------------------
// Inputs (metadata order): query [B,D] f32, attend_to [B,T,D] f32,
// mask [T,B] bool->int32, W [D,D] f32, b [D] f32. Output: [B,1,D] f32.
// ---------------------------------------------------------------------------
extern "C" void kernel_launch(void* const* d_in, const int* in_sizes, int n_in,
                              void* d_out, int out_size) {
    const float* query  = (const float*)d_in[0];
    const float* attend = (const float*)d_in[1];
    const int*   mask   = (const int*)d_in[2];
    const float* W      = (const float*)d_in[3];
    const float* bias   = (const float*)d_in[4];
    float* out = (float*)d_out;

    key_kernel<<<B, 512>>>(query, W, bias);
    attn_partial_kernel<<<dim3(SPLITS, B), THREADS>>>(attend, mask);
    combine_kernel<<<B, 256>>>(out);
}

// round 9
// speedup vs baseline: 1.9617x; 1.9617x over previous
#include <cuda_runtime.h>
#include <math.h>

#define B 64
#define T 4096
#define D 512
#define SPLITS 16
#define CHUNK (T / SPLITS)     // 256 rows of T per CTA
#define THREADS 256            // 8 warps per CTA
#define ROWS_PER_WARP (CHUNK / 8)   // 32

// Scratch (no allocation allowed anywhere)
__device__ float g_k[B * D];                    // key = query @ W^T + b
__device__ float g_pm[B * SPLITS];              // partial max
__device__ float g_ps[B * SPLITS];              // partial sum
__device__ float g_pacc[B * SPLITS * D];        // partial weighted accumulators

// ---------------------------------------------------------------------------
// Kernel 1: k[b, d] = dot(query[b,:], W[d,:]) + bias[d].
// One warp per output element: lane-strided float4 loads + butterfly reduce.
// grid = B*D/8 warps / 8 warps-per-block = 4096 blocks. W stays in L2.
// ---------------------------------------------------------------------------
__global__ __launch_bounds__(256)
void key_kernel(const float* __restrict__ query,
                const float* __restrict__ W,
                const float* __restrict__ bias) {
    const int wid  = threadIdx.x >> 5;
    const int lane = threadIdx.x & 31;
    const int gw   = blockIdx.x * 8 + wid;      // 0 .. B*D-1
    const int b    = gw >> 9;                   // gw / D
    const int d    = gw & (D - 1);              // gw % D

    const float4* Wp = (const float4*)(W + (size_t)d * D);
    const float4* qp = (const float4*)(query + (size_t)b * D);

    float p0 = 0.f, p1 = 0.f, p2 = 0.f, p3 = 0.f;
    #pragma unroll
    for (int j = 0; j < 4; j++) {
        float4 w4 = Wp[lane + 32 * j];
        float4 q4 = qp[lane + 32 * j];
        p0 = fmaf(w4.x, q4.x, p0);
        p1 = fmaf(w4.y, q4.y, p1);
        p2 = fmaf(w4.z, q4.z, p2);
        p3 = fmaf(w4.w, q4.w, p3);
    }
    float sum = (p0 + p1) + (p2 + p3);
    #pragma unroll
    for (int off = 16; off; off >>= 1)
        sum += __shfl_xor_sync(0xffffffffu, sum, off);
    if (lane == 0) g_k[(size_t)b * D + d] = sum + bias[d];
}

// ---------------------------------------------------------------------------
// Kernel 2: fused scores + masked online softmax + weighted accumulation.
// grid = (SPLITS, B). Warp-owns-row register streaming: lane l holds columns
// {128j + 4l .. +3} (j=0..3) of each row in registers, k slice in registers,
// private per-lane (m, s, acc[16]) online state. NO smem / NO barriers in the
// hot loop. End-phase: 8-warp smem combine -> one CTA partial.
// ---------------------------------------------------------------------------
__global__ __launch_bounds__(THREADS)
void attn_partial_kernel(const float* __restrict__ attend_to,
                         const int* __restrict__ mask) {   // bool -> int32
    const int b    = blockIdx.y;
    const int sp   = blockIdx.x;
    const int tid  = threadIdx.x;
    const int wid  = tid >> 5;
    const int lane = tid & 31;
    const int trow0 = sp * CHUNK + wid * ROWS_PER_WARP;    // first row of warp

    // k slice for this lane (16 floats, registers)
    const float4* kp = (const float4*)(g_k + (size_t)b * D);
    const float4 k0 = kp[lane], k1 = kp[lane + 32],
                 k2 = kp[lane + 64], k3 = kp[lane + 96];

    // Pre-gather this warp's 32 mask bits into one ballot word.
    const int mv = __ldg(&mask[(size_t)(trow0 + lane) * B + b]);
    const unsigned mbits = __ballot_sync(0xffffffffu, mv != 0);

    const float4* rp = (const float4*)(attend_to +
                                       ((size_t)b * T + trow0) * D);
    // float4 index of lane's slice within a row; rows advance by D/4 = 128.
    float4 c0 = rp[lane], c1 = rp[lane + 32],
           c2 = rp[lane + 64], c3 = rp[lane + 96];

    float m = -INFINITY, s = 0.f;
    float4 a0 = {0,0,0,0}, a1 = {0,0,0,0}, a2 = {0,0,0,0}, a3 = {0,0,0,0};

    #pragma unroll 2
    for (int i = 0; i < ROWS_PER_WARP; i++) {
        // Prefetch next row into registers (independent of current compute)
        float4 n0, n1, n2, n3;
        if (i + 1 < ROWS_PER_WARP) {
            const float4* nr = rp + (size_t)(i + 1) * (D / 4);
            n0 = nr[lane]; n1 = nr[lane + 32];
            n2 = nr[lane + 64]; n3 = nr[lane + 96];
        }

        // Row dot product: 4 independent partial chains, then combine
        float p0 = c0.x * k0.x + c0.y * k0.y + c0.z * k0.z + c0.w * k0.w;
        float p1 = c1.x * k1.x + c1.y * k1.y + c1.z * k1.z + c1.w * k1.w;
        float p2 = c2.x * k2.x + c2.y * k2.y + c2.z * k2.z + c2.w * k2.w;
        float p3 = c3.x * k3.x + c3.y * k3.y + c3.z * k3.z + c3.w * k3.w;
        float sc = (p0 + p1) + (p2 + p3);
        #pragma unroll
        for (int off = 16; off; off >>= 1)
            sc += __shfl_xor_sync(0xffffffffu, sc, off);
        if ((mbits >> i) & 1u) sc = -INFINITY;

        // Online softmax update (warp-uniform branches: sc uniform in warp)
        if (sc > m) {
            // New max (also handles first unmasked row: m=-inf -> corr=0)
            float corr = __expf(m - sc);
            s = s * corr + 1.0f;
            a0.x = fmaf(a0.x, corr, c0.x); a0.y = fmaf(a0.y, corr, c0.y);
            a0.z = fmaf(a0.z, corr, c0.z); a0.w = fmaf(a0.w, corr, c0.w);
            a1.x = fmaf(a1.x, corr, c1.x); a1.y = fmaf(a1.y, corr, c1.y);
            a1.z = fmaf(a1.z, corr, c1.z); a1.w = fmaf(a1.w, corr, c1.w);
            a2.x = fmaf(a2.x, corr, c2.x); a2.y = fmaf(a2.y, corr, c2.y);
            a2.z = fmaf(a2.z, corr, c2.z); a2.w = fmaf(a2.w, corr, c2.w);
            a3.x = fmaf(a3.x, corr, c3.x); a3.y = fmaf(a3.y, corr, c3.y);
            a3.z = fmaf(a3.z, corr, c3.z); a3.w = fmaf(a3.w, corr, c3.w);
            m = sc;
        } else if (sc != -INFINITY) {
            // Common path: no rescale, one exp + 16 fma
            float p = __expf(sc - m);
            s += p;
            a0.x = fmaf(p, c0.x, a0.x); a0.y = fmaf(p, c0.y, a0.y);
            a0.z = fmaf(p, c0.z, a0.z); a0.w = fmaf(p, c0.w, a0.w);
            a1.x = fmaf(p, c1.x, a1.x); a1.y = fmaf(p, c1.y, a1.y);
            a1.z = fmaf(p, c1.z, a1.z); a1.w = fmaf(p, c1.w, a1.w);
            a2.x = fmaf(p, c2.x, a2.x); a2.y = fmaf(p, c2.y, a2.y);
            a2.z = fmaf(p, c2.z, a2.z); a2.w = fmaf(p, c2.w, a2.w);
            a3.x = fmaf(p, c3.x, a3.x); a3.y = fmaf(p, c3.y, a3.y);
            a3.z = fmaf(p, c3.z, a3.z); a3.w = fmaf(p, c3.w, a3.w);
        }
        c0 = n0; c1 = n1; c2 = n2; c3 = n3;
    }

    // ---- End-phase: combine the 8 warps' partials into one CTA partial ----
    __shared__ float4 sm_acc[8][D / 4];   // 16 KB
    __shared__ float  sm_m[8], sm_s[8];

    sm_acc[wid][lane]      = a0;
    sm_acc[wid][lane + 32] = a1;
    sm_acc[wid][lane + 64] = a2;
    sm_acc[wid][lane + 96] = a3;
    if (lane == 0) { sm_m[wid] = m; sm_s[wid] = s; }
    __syncthreads();

    float M = -INFINITY;
    #pragma unroll
    for (int w = 0; w < 8; w++) M = fmaxf(M, sm_m[w]);
    float wts[8];
    float stot = 0.f;
    #pragma unroll
    for (int w = 0; w < 8; w++) {
        float mw = sm_m[w];
        float wt = (mw == -INFINITY) ? 0.f : __expf(mw - M);
        wts[w] = wt;
        stot += wt * sm_s[w];
    }

    const float* sa = (const float*)sm_acc;   // [8][512]
    float v0 = 0.f, v1 = 0.f;
    #pragma unroll
    for (int w = 0; w < 8; w++) {
        v0 += wts[w] * sa[w * D + tid];
        v1 += wts[w] * sa[w * D + tid + THREADS];
    }

    const int pi = b * SPLITS + sp;
    g_pacc[(size_t)pi * D + tid]           = v0;
    g_pacc[(size_t)pi * D + tid + THREADS] = v1;
    if (tid == 0) { g_pm[pi] = M; g_ps[pi] = stot; }
}

// ---------------------------------------------------------------------------
// Kernel 3: combine SPLITS partials per batch row. grid = (B, 2).
// ---------------------------------------------------------------------------
__global__ __launch_bounds__(256)
void combine_kernel(float* __restrict__ out) {
    const int b = blockIdx.x;
    const int c = blockIdx.y * 256 + threadIdx.x;

    float M = -INFINITY;
    #pragma unroll
    for (int i = 0; i < SPLITS; i++) M = fmaxf(M, g_pm[b * SPLITS + i]);

    float stot = 0.f, sum = 0.f;
    #pragma unroll
    for (int i = 0; i < SPLITS; i++) {
        float mi = g_pm[b * SPLITS + i];
        float w = (mi == -INFINITY) ? 0.f : __expf(mi - M);
        stot += g_ps[b * SPLITS + i] * w;
        sum  += g_pacc[(size_t)(b * SPLITS + i) * D + c] * w;
    }
    out[(size_t)b * D + c] = sum / stot;
}

// ---------------------------------------------------------------------------
// Inputs (metadata order): query [B,D] f32, attend_to [B,T,D] f32,
// mask [T,B] bool->int32, W [D,D] f32, b [D] f32. Output: [B,1,D] f32.
// ---------------------------------------------------------------------------
extern "C" void kernel_launch(void* const* d_in, const int* in_sizes, int n_in,
                              void* d_out, int out_size) {
    const float* query  = (const float*)d_in[0];
    const float* attend = (const float*)d_in[1];
    const int*   mask   = (const int*)d_in[2];
    const float* W      = (const float*)d_in[3];
    const float* bias   = (const float*)d_in[4];
    float* out = (float*)d_out;

    key_kernel<<<(B * D) / 8, 256>>>(query, W, bias);
    attn_partial_kernel<<<dim3(SPLITS, B), THREADS>>>(attend, mask);
    combine_kernel<<<dim3(B, 2), 256>>>(out);
}

// round 12
// speedup vs baseline: 2.0721x; 1.0563x over previous
#include <cuda_runtime.h>
#include <math.h>

#define B 64
#define T 4096
#define D 512
#define SPLITS 32
#define CHUNK (T / SPLITS)          // 128 rows of T per CTA
#define THREADS 256                 // 8 warps per CTA
#define ROWS_PER_WARP (CHUNK / 8)   // 16

// Scratch (no allocation allowed anywhere)
__device__ float g_k[B * D];
__device__ float g_pm[B * SPLITS];
__device__ float g_ps[B * SPLITS];
__device__ float g_pacc[B * SPLITS * D];        // 4 MB

// ---------------------------------------------------------------------------
// Kernel 1: k = query @ W^T + bias.  Warp computes a 4b x 4d tile:
// 4 W-row slices live in registers, 4 q rows streamed. Halves L2 traffic
// (32 MB) vs warp-per-output and quadruples FMA/byte.
// grid = 2048 warps / 8 = 256 blocks.
// ---------------------------------------------------------------------------
__global__ __launch_bounds__(256)
void key_kernel(const float* __restrict__ query,
                const float* __restrict__ W,
                const float* __restrict__ bias) {
    const int wid  = threadIdx.x >> 5;
    const int lane = threadIdx.x & 31;
    const int warp = blockIdx.x * 8 + wid;      // 0..2047
    const int d0   = (warp & 127) * 4;          // 128 d-tiles
    const int b0   = (warp >> 7) * 4;           // 16  b-tiles

    const float4* Wp = (const float4*)W;        // row = 128 float4
    const float4* Qp = (const float4*)query;

    float4 w[4][4];
    #pragma unroll
    for (int i = 0; i < 4; i++)
        #pragma unroll
        for (int j = 0; j < 4; j++)
            w[i][j] = Wp[(size_t)(d0 + i) * 128 + lane + 32 * j];

    #pragma unroll
    for (int bi = 0; bi < 4; bi++) {
        float4 q4[4];
        #pragma unroll
        for (int j = 0; j < 4; j++)
            q4[j] = Qp[(size_t)(b0 + bi) * 128 + lane + 32 * j];

        float p[4];
        #pragma unroll
        for (int i = 0; i < 4; i++) {
            float s0 = 0.f, s1 = 0.f, s2 = 0.f, s3 = 0.f;
            #pragma unroll
            for (int j = 0; j < 4; j++) {
                s0 = fmaf(w[i][j].x, q4[j].x, s0);
                s1 = fmaf(w[i][j].y, q4[j].y, s1);
                s2 = fmaf(w[i][j].z, q4[j].z, s2);
                s3 = fmaf(w[i][j].w, q4[j].w, s3);
            }
            p[i] = (s0 + s1) + (s2 + s3);
        }
        #pragma unroll
        for (int off = 16; off; off >>= 1)
            #pragma unroll
            for (int i = 0; i < 4; i++)
                p[i] += __shfl_xor_sync(0xffffffffu, p[i], off);
        if (lane == 0) {
            #pragma unroll
            for (int i = 0; i < 4; i++)
                g_k[(size_t)(b0 + bi) * D + d0 + i] = p[i] + bias[d0 + i];
        }
    }
}

// ---------------------------------------------------------------------------
// Kernel 2: fused scores + masked online softmax + weighted accumulation.
// grid = (SPLITS, B). Warp-owns-row register streaming; k slice read from
// smem per row (frees 16 regs); launch_bounds forces 3 CTAs/SM for MLP.
// ---------------------------------------------------------------------------
__global__ __launch_bounds__(THREADS, 3)
void attn_partial_kernel(const float* __restrict__ attend_to,
                         const int* __restrict__ mask) {   // bool -> int32
    __shared__ float  k_sh[D];                 // 2 KB
    __shared__ float4 sm_acc[8][D / 4];        // 16 KB (end-phase)
    __shared__ float  sm_m[8], sm_s[8];

    const int b    = blockIdx.y;
    const int sp   = blockIdx.x;
    const int tid  = threadIdx.x;
    const int wid  = tid >> 5;
    const int lane = tid & 31;
    const int trow0 = sp * CHUNK + wid * ROWS_PER_WARP;

    for (int i = tid; i < D; i += THREADS) k_sh[i] = g_k[(size_t)b * D + i];

    // Warp's ROWS_PER_WARP(=16) mask bits gathered into one ballot word.
    int mv = 0;
    if (lane < ROWS_PER_WARP)
        mv = __ldg(&mask[(size_t)(trow0 + lane) * B + b]);
    const unsigned mbits = __ballot_sync(0xffffffffu, mv != 0);

    const float4* rp = (const float4*)(attend_to + ((size_t)b * T + trow0) * D);
    float4 c0 = rp[lane], c1 = rp[lane + 32],
           c2 = rp[lane + 64], c3 = rp[lane + 96];

    __syncthreads();                           // k_sh ready
    const float4* ks4 = (const float4*)k_sh;

    float m = -INFINITY, s = 0.f;
    float4 a0 = {0,0,0,0}, a1 = {0,0,0,0}, a2 = {0,0,0,0}, a3 = {0,0,0,0};

    #pragma unroll 2
    for (int i = 0; i < ROWS_PER_WARP; i++) {
        // Prefetch next row into registers
        float4 n0, n1, n2, n3;
        if (i + 1 < ROWS_PER_WARP) {
            const float4* nr = rp + (size_t)(i + 1) * (D / 4);
            n0 = nr[lane]; n1 = nr[lane + 32];
            n2 = nr[lane + 64]; n3 = nr[lane + 96];
        }

        // Row dot with k (k slice from smem, transient regs)
        float4 kv = ks4[lane];
        float p0 = c0.x * kv.x + c0.y * kv.y + c0.z * kv.z + c0.w * kv.w;
        kv = ks4[lane + 32];
        float p1 = c1.x * kv.x + c1.y * kv.y + c1.z * kv.z + c1.w * kv.w;
        kv = ks4[lane + 64];
        float p2 = c2.x * kv.x + c2.y * kv.y + c2.z * kv.z + c2.w * kv.w;
        kv = ks4[lane + 96];
        float p3 = c3.x * kv.x + c3.y * kv.y + c3.z * kv.z + c3.w * kv.w;
        float sc = (p0 + p1) + (p2 + p3);
        #pragma unroll
        for (int off = 16; off; off >>= 1)
            sc += __shfl_xor_sync(0xffffffffu, sc, off);
        if ((mbits >> i) & 1u) sc = -INFINITY;

        // Online softmax update (branches warp-uniform)
        if (sc > m) {
            float corr = __expf(m - sc);       // m=-inf -> corr=0 on first row
            s = s * corr + 1.0f;
            a0.x = fmaf(a0.x, corr, c0.x); a0.y = fmaf(a0.y, corr, c0.y);
            a0.z = fmaf(a0.z, corr, c0.z); a0.w = fmaf(a0.w, corr, c0.w);
            a1.x = fmaf(a1.x, corr, c1.x); a1.y = fmaf(a1.y, corr, c1.y);
            a1.z = fmaf(a1.z, corr, c1.z); a1.w = fmaf(a1.w, corr, c1.w);
            a2.x = fmaf(a2.x, corr, c2.x); a2.y = fmaf(a2.y, corr, c2.y);
            a2.z = fmaf(a2.z, corr, c2.z); a2.w = fmaf(a2.w, corr, c2.w);
            a3.x = fmaf(a3.x, corr, c3.x); a3.y = fmaf(a3.y, corr, c3.y);
            a3.z = fmaf(a3.z, corr, c3.z); a3.w = fmaf(a3.w, corr, c3.w);
            m = sc;
        } else if (sc != -INFINITY) {
            float p = __expf(sc - m);
            s += p;
            a0.x = fmaf(p, c0.x, a0.x); a0.y = fmaf(p, c0.y, a0.y);
            a0.z = fmaf(p, c0.z, a0.z); a0.w = fmaf(p, c0.w, a0.w);
            a1.x = fmaf(p, c1.x, a1.x); a1.y = fmaf(p, c1.y, a1.y);
            a1.z = fmaf(p, c1.z, a1.z); a1.w = fmaf(p, c1.w, a1.w);
            a2.x = fmaf(p, c2.x, a2.x); a2.y = fmaf(p, c2.y, a2.y);
            a2.z = fmaf(p, c2.z, a2.z); a2.w = fmaf(p, c2.w, a2.w);
            a3.x = fmaf(p, c3.x, a3.x); a3.y = fmaf(p, c3.y, a3.y);
            a3.z = fmaf(p, c3.z, a3.z); a3.w = fmaf(p, c3.w, a3.w);
        }
        c0 = n0; c1 = n1; c2 = n2; c3 = n3;
    }

    // ---- End-phase: combine 8 warps -> one CTA partial ----
    sm_acc[wid][lane]      = a0;
    sm_acc[wid][lane + 32] = a1;
    sm_acc[wid][lane + 64] = a2;
    sm_acc[wid][lane + 96] = a3;
    if (lane == 0) { sm_m[wid] = m; sm_s[wid] = s; }
    __syncthreads();

    float M = -INFINITY;
    #pragma unroll
    for (int w = 0; w < 8; w++) M = fmaxf(M, sm_m[w]);
    float wts[8];
    float stot = 0.f;
    #pragma unroll
    for (int w = 0; w < 8; w++) {
        float mw = sm_m[w];
        float wt = (mw == -INFINITY) ? 0.f : __expf(mw - M);
        wts[w] = wt;
        stot += wt * sm_s[w];
    }

    const float* sa = (const float*)sm_acc;   // [8][512]
    float v0 = 0.f, v1 = 0.f;
    #pragma unroll
    for (int w = 0; w < 8; w++) {
        v0 += wts[w] * sa[w * D + tid];
        v1 += wts[w] * sa[w * D + tid + THREADS];
    }

    const int pi = b * SPLITS + sp;
    g_pacc[(size_t)pi * D + tid]           = v0;
    g_pacc[(size_t)pi * D + tid + THREADS] = v1;
    if (tid == 0) { g_pm[pi] = M; g_ps[pi] = stot; }
}

// ---------------------------------------------------------------------------
// Kernel 3: combine SPLITS partials per batch row. grid = (B, 2).
// ---------------------------------------------------------------------------
__global__ __launch_bounds__(256)
void combine_kernel(float* __restrict__ out) {
    const int b = blockIdx.x;
    const int c = blockIdx.y * 256 + threadIdx.x;

    float M = -INFINITY;
    #pragma unroll
    for (int i = 0; i < SPLITS; i++) M = fmaxf(M, g_pm[b * SPLITS + i]);

    float stot = 0.f, sum = 0.f;
    #pragma unroll
    for (int i = 0; i < SPLITS; i++) {
        float mi = g_pm[b * SPLITS + i];
        float w = (mi == -INFINITY) ? 0.f : __expf(mi - M);
        stot += g_ps[b * SPLITS + i] * w;
        sum  += g_pacc[(size_t)(b * SPLITS + i) * D + c] * w;
    }
    out[(size_t)b * D + c] = sum / stot;
}

// ---------------------------------------------------------------------------
// Inputs (metadata order): query [B,D] f32, attend_to [B,T,D] f32,
// mask [T,B] bool->int32, W [D,D] f32, b [D] f32. Output: [B,1,D] f32.
// ---------------------------------------------------------------------------
extern "C" void kernel_launch(void* const* d_in, const int* in_sizes, int n_in,
                              void* d_out, int out_size) {
    const float* query  = (const float*)d_in[0];
    const float* attend = (const float*)d_in[1];
    const int*   mask   = (const int*)d_in[2];
    const float* W      = (const float*)d_in[3];
    const float* bias   = (const float*)d_in[4];
    float* out = (float*)d_out;

    key_kernel<<<256, 256>>>(query, W, bias);
    attn_partial_kernel<<<dim3(SPLITS, B), THREADS>>>(attend, mask);
    combine_kernel<<<dim3(B, 2), 256>>>(out);
}